// round 3
// baseline (speedup 1.0000x reference)
#include <cuda_runtime.h>

#define DIM 128
#define MAX_NODES 50000
#define MAX_EDGES 800000

// Scratch (device globals — no allocation allowed)
__device__ float g_h[MAX_NODES * DIM];       // h = x @ W^T
__device__ float g_dinv[MAX_NODES];
__device__ int   g_cnt_row[MAX_NODES];       // in-degree by destination (row)
__device__ int   g_cnt_col[MAX_NODES];       // degree by col (for normalization)
__device__ int   g_rowptr[MAX_NODES + 1];
__device__ int   g_cursor[MAX_NODES];
__device__ int   g_ecol[MAX_EDGES];          // CSR adjacency (source node ids)
__device__ int   g_is64;                     // 1 if edge_index is int64

// ---------------------------------------------------------------------------
// Detect edge_index dtype: int64 (little-endian, values < 2^31) has every odd
// 32-bit word == 0; random int32 edge data does not (p ~ 0 over 2048 words).
// ---------------------------------------------------------------------------
__global__ void k_detect(const int* __restrict__ p, int n_elems) {
    if (blockIdx.x == 0 && threadIdx.x == 0) {
        int lim = n_elems < 4096 ? n_elems : 4096;  // safe: >= n_elems int32 words exist
        int is64 = 1;
        for (int i = 1; i < lim; i += 2)
            if (p[i] != 0) { is64 = 0; break; }
        g_is64 = is64;
    }
}

__device__ __forceinline__ int edge_at(const int* __restrict__ p, int idx) {
    return g_is64 ? p[2 * idx] : p[idx];
}

// ---------------------------------------------------------------------------
__global__ void k_zero(int N) {
    int i = blockIdx.x * blockDim.x + threadIdx.x;
    if (i < N) { g_cnt_row[i] = 0; g_cnt_col[i] = 0; }
}

// Histogram rows (CSR) and cols (degree)
__global__ void k_count(const int* __restrict__ p, int E) {
    int e = blockIdx.x * blockDim.x + threadIdx.x;
    if (e < E) {
        atomicAdd(&g_cnt_row[edge_at(p, e)], 1);
        atomicAdd(&g_cnt_col[edge_at(p, E + e)], 1);
    }
}

__global__ void k_dinv(int N) {
    int i = blockIdx.x * blockDim.x + threadIdx.x;
    if (i < N) g_dinv[i] = rsqrtf(1.0f + (float)g_cnt_col[i]);  // +1 self-loop
}

// ---------------------------------------------------------------------------
// Exclusive scan of cnt_row -> rowptr (single block, chunked)
// ---------------------------------------------------------------------------
__global__ __launch_bounds__(1024) void k_scan(int N) {
    __shared__ int sums[1024];
    int t = threadIdx.x;
    int chunk = (N + 1023) / 1024;
    int base = t * chunk;
    int s = 0;
    for (int i = 0; i < chunk; i++) {
        int idx = base + i;
        if (idx < N) s += g_cnt_row[idx];
    }
    sums[t] = s;
    __syncthreads();
    for (int off = 1; off < 1024; off <<= 1) {
        int v = (t >= off) ? sums[t - off] : 0;
        __syncthreads();
        sums[t] += v;
        __syncthreads();
    }
    int run = sums[t] - s;  // exclusive prefix for this chunk
    for (int i = 0; i < chunk; i++) {
        int idx = base + i;
        if (idx < N) {
            g_rowptr[idx] = run;
            g_cursor[idx] = run;
            run += g_cnt_row[idx];
        }
    }
    if (t == 1023) g_rowptr[N] = sums[1023];
}

// Fill CSR adjacency
__global__ void k_fill(const int* __restrict__ p, int E) {
    int e = blockIdx.x * blockDim.x + threadIdx.x;
    if (e < E) {
        int r = edge_at(p, e);
        int c = edge_at(p, E + e);
        int pos = atomicAdd(&g_cursor[r], 1);
        g_ecol[pos] = c;
    }
}

// ---------------------------------------------------------------------------
// GEMM: h[m][c] = sum_k x[m][k] * W[c][k]
// 64 rows/block, 256 threads, 8x4 register tile, K chunks of 32 staged
// transposed in shared (padded strides -> conflict-free float4 LDS).
// ---------------------------------------------------------------------------
#define TM 64
#define KC 32
#define WT_STRIDE 132
#define XT_STRIDE 68

__global__ __launch_bounds__(256) void k_gemm(const float* __restrict__ x,
                                              const float* __restrict__ W, int N) {
    __shared__ float Wt[KC * WT_STRIDE];  // Wt[kk][c]
    __shared__ float xt[KC * XT_STRIDE];  // xt[kk][m]

    int t = threadIdx.x;
    int m_base = blockIdx.x * TM;
    int c0 = (t & 31) * 4;
    int m0 = (t >> 5) * 8;

    float acc[8][4];
#pragma unroll
    for (int i = 0; i < 8; i++)
#pragma unroll
        for (int j = 0; j < 4; j++) acc[i][j] = 0.0f;

    for (int kb = 0; kb < DIM; kb += KC) {
        __syncthreads();
        for (int i = t; i < DIM * KC; i += 256) {
            int kk = i & (KC - 1);
            int c  = i >> 5;
            Wt[kk * WT_STRIDE + c] = W[c * DIM + kb + kk];
        }
        for (int i = t; i < TM * KC; i += 256) {
            int kk = i & (KC - 1);
            int m  = i >> 5;
            int gm = m_base + m;
            xt[kk * XT_STRIDE + m] = (gm < N) ? x[(size_t)gm * DIM + kb + kk] : 0.0f;
        }
        __syncthreads();

#pragma unroll 4
        for (int kk = 0; kk < KC; kk++) {
            float4 wv = *(const float4*)&Wt[kk * WT_STRIDE + c0];
            float4 xa = *(const float4*)&xt[kk * XT_STRIDE + m0];
            float4 xb = *(const float4*)&xt[kk * XT_STRIDE + m0 + 4];
            float xr[8] = {xa.x, xa.y, xa.z, xa.w, xb.x, xb.y, xb.z, xb.w};
#pragma unroll
            for (int i = 0; i < 8; i++) {
                acc[i][0] += xr[i] * wv.x;
                acc[i][1] += xr[i] * wv.y;
                acc[i][2] += xr[i] * wv.z;
                acc[i][3] += xr[i] * wv.w;
            }
        }
    }

#pragma unroll
    for (int i = 0; i < 8; i++) {
        int gm = m_base + m0 + i;
        if (gm < N) {
            *(float4*)&g_h[(size_t)gm * DIM + c0] =
                make_float4(acc[i][0], acc[i][1], acc[i][2], acc[i][3]);
        }
    }
}

// ---------------------------------------------------------------------------
// Gather: one warp per destination node. Lane l owns floats [4l, 4l+4).
// out[i] = relu( dinv[i]^2 * h[i] + sum_j dinv[i]*dinv[col_j] * h[col_j] )
// ---------------------------------------------------------------------------
__global__ __launch_bounds__(256) void k_gather(float* __restrict__ out, int N) {
    int gtid = blockIdx.x * blockDim.x + threadIdx.x;
    int i = gtid >> 5;
    int lane = gtid & 31;
    if (i >= N) return;

    float di = g_dinv[i];
    float4 hv = ((const float4*)(g_h + (size_t)i * DIM))[lane];
    float s = di * di;
    float4 acc = make_float4(hv.x * s, hv.y * s, hv.z * s, hv.w * s);

    int start = g_rowptr[i];
    int end   = g_rowptr[i + 1];

    for (int b = start; b < end; b += 32) {
        int j = b + lane;
        int col = 0;
        float wl = 0.0f;
        if (j < end) {
            col = g_ecol[j];
            wl = di * g_dinv[col];
        }
        int cnt = min(32, end - b);
        for (int t = 0; t < cnt; t++) {
            int   cc = __shfl_sync(0xFFFFFFFFu, col, t);
            float ww = __shfl_sync(0xFFFFFFFFu, wl, t);
            float4 nv = ((const float4*)(g_h + (size_t)cc * DIM))[lane];
            acc.x += ww * nv.x;
            acc.y += ww * nv.y;
            acc.z += ww * nv.z;
            acc.w += ww * nv.w;
        }
    }

    acc.x = fmaxf(acc.x, 0.0f);
    acc.y = fmaxf(acc.y, 0.0f);
    acc.z = fmaxf(acc.z, 0.0f);
    acc.w = fmaxf(acc.w, 0.0f);
    ((float4*)(out + (size_t)i * DIM))[lane] = acc;
}

// ---------------------------------------------------------------------------
extern "C" void kernel_launch(void* const* d_in, const int* in_sizes, int n_in,
                              void* d_out, int out_size) {
    const float* x   = (const float*)d_in[0];
    const float* W   = (const float*)d_in[1];
    const int*   ei  = (const int*)d_in[2];   // int32 words; int64 handled via g_is64
    float* out       = (float*)d_out;

    int N = in_sizes[0] / DIM;
    int E = in_sizes[2] / 2;

    k_detect<<<1, 32>>>(ei, in_sizes[2]);
    k_zero<<<(N + 255) / 256, 256>>>(N);
    k_count<<<(E + 255) / 256, 256>>>(ei, E);
    k_dinv<<<(N + 255) / 256, 256>>>(N);
    k_scan<<<1, 1024>>>(N);
    k_fill<<<(E + 255) / 256, 256>>>(ei, E);
    k_gemm<<<(N + TM - 1) / TM, 256>>>(x, W, N);
    k_gather<<<(N * 32 + 255) / 256, 256>>>(out, N);
}

// round 4
// speedup vs baseline: 1.6010x; 1.6010x over previous
#include <cuda_runtime.h>

#define DIM 128
#define MAX_NODES 50000
#define MAX_EDGES 800000

typedef unsigned long long ull;

// Scratch (device globals — no allocation allowed)
__device__ float g_h[MAX_NODES * DIM];       // h = x @ W^T
__device__ float g_dinv[MAX_NODES];
__device__ int   g_cnt_row[MAX_NODES];       // in-degree by destination (row)
__device__ int   g_cnt_col[MAX_NODES];       // degree by col (for normalization)
__device__ int   g_rowptr[MAX_NODES];
__device__ int   g_rowend[MAX_NODES];
__device__ int   g_cursor[MAX_NODES];
__device__ int2  g_edge[MAX_EDGES];          // packed (col, bits(dinv[col]))
__device__ int   g_total;
__device__ int   g_is64;                     // 1 if edge_index is int64

// f32x2 packed math (SASS FFMA2 — only reachable via PTX)
#define FMA2(d, a, b, c) \
    asm("fma.rn.f32x2 %0, %1, %2, %3;" : "=l"(d) : "l"(a), "l"(b), "l"(c))
#define PACK2(d, lo, hi) \
    asm("mov.b64 %0, {%1, %2};" : "=l"(d) : "f"(lo), "f"(hi))
#define UNPACK2(lo, hi, v) \
    asm("mov.b64 {%0, %1}, %2;" : "=f"(lo), "=f"(hi) : "l"(v))

__device__ __forceinline__ int edge_at(const int* __restrict__ p, int idx) {
    return g_is64 ? p[2 * idx] : p[idx];
}

// ---------------------------------------------------------------------------
// Prep: zero counters + global cursor; warp-parallel dtype detect.
// int64 (LE, values < 2^31): every odd 32-bit word of the buffer is 0.
// ---------------------------------------------------------------------------
__global__ void k_prep(const int* __restrict__ p, int n_elems, int N) {
    int i = blockIdx.x * blockDim.x + threadIdx.x;
    if (i < N) { g_cnt_row[i] = 0; g_cnt_col[i] = 0; }
    if (i == 0) g_total = 0;
    if (blockIdx.x == 0 && threadIdx.x < 32) {
        int lim = n_elems < 4096 ? n_elems : 4096;  // words available >= n_elems
        int bad = 0;
        for (int w = threadIdx.x; 2 * w + 1 < lim; w += 32)
            if (p[2 * w + 1] != 0) bad = 1;
        unsigned m = __ballot_sync(0xFFFFFFFFu, bad);
        if (threadIdx.x == 0) g_is64 = (m == 0) ? 1 : 0;
    }
}

// Histogram rows (CSR) and cols (degree)
__global__ void k_count(const int* __restrict__ p, int E) {
    int e = blockIdx.x * blockDim.x + threadIdx.x;
    if (e < E) {
        atomicAdd(&g_cnt_row[edge_at(p, e)], 1);
        atomicAdd(&g_cnt_col[edge_at(p, E + e)], 1);
    }
}

// ---------------------------------------------------------------------------
// dinv + CSR range allocation (warp-aggregated atomic base; no global scan,
// ranges need not be monotonic — gather only needs per-node [start, end)).
// ---------------------------------------------------------------------------
__global__ __launch_bounds__(256) void k_alloc(int N) {
    int i = blockIdx.x * blockDim.x + threadIdx.x;
    int lane = threadIdx.x & 31;
    int c = (i < N) ? g_cnt_row[i] : 0;
    if (i < N) g_dinv[i] = rsqrtf(1.0f + (float)g_cnt_col[i]);  // +1 self-loop

    // warp inclusive scan of c
    int incl = c;
#pragma unroll
    for (int o = 1; o < 32; o <<= 1) {
        int v = __shfl_up_sync(0xFFFFFFFFu, incl, o);
        if (lane >= o) incl += v;
    }
    int base = 0;
    if (lane == 31) base = atomicAdd(&g_total, incl);
    base = __shfl_sync(0xFFFFFFFFu, base, 31);
    int start = base + incl - c;
    if (i < N) {
        g_rowptr[i] = start;
        g_cursor[i] = start;
        g_rowend[i] = start + c;
    }
}

// Fill CSR adjacency with packed (col, dinv[col])
__global__ void k_fill(const int* __restrict__ p, int E) {
    int e = blockIdx.x * blockDim.x + threadIdx.x;
    if (e < E) {
        int r = edge_at(p, e);
        int c = edge_at(p, E + e);
        int pos = atomicAdd(&g_cursor[r], 1);
        g_edge[pos] = make_int2(c, __float_as_int(g_dinv[c]));
    }
}

// ---------------------------------------------------------------------------
// GEMM: h[m][c] = sum_k x[m][k] * W[c][k]
// 64 rows/block, 256 threads, 8x4 register tile via packed f32x2 FMA.
// Mainloop LDS: W warp-contiguous 512B (conflict-free), x broadcast.
// ---------------------------------------------------------------------------
#define TM 64
#define KC 32
#define WT_STRIDE 132
#define XT_STRIDE 68

__global__ __launch_bounds__(256) void k_gemm(const float* __restrict__ x,
                                              const float* __restrict__ W, int N) {
    __shared__ float Wt[KC * WT_STRIDE];  // Wt[kk][c]
    __shared__ float xt[KC * XT_STRIDE];  // xt[kk][m]

    int t = threadIdx.x;
    int m_base = blockIdx.x * TM;
    int c0 = (t & 31) * 4;
    int m0 = (t >> 5) * 8;

    ull a01[8], a23[8];
#pragma unroll
    for (int i = 0; i < 8; i++) { a01[i] = 0ull; a23[i] = 0ull; }

    for (int kb = 0; kb < DIM; kb += KC) {
        __syncthreads();
        for (int i = t; i < DIM * KC; i += 256) {
            int kk = i & (KC - 1);
            int c  = i >> 5;
            Wt[kk * WT_STRIDE + c] = W[c * DIM + kb + kk];
        }
        for (int i = t; i < TM * KC; i += 256) {
            int kk = i & (KC - 1);
            int m  = i >> 5;
            int gm = m_base + m;
            xt[kk * XT_STRIDE + m] = (gm < N) ? x[(size_t)gm * DIM + kb + kk] : 0.0f;
        }
        __syncthreads();

#pragma unroll 4
        for (int kk = 0; kk < KC; kk++) {
            float4 wv = *(const float4*)&Wt[kk * WT_STRIDE + c0];
            ull b01, b23;
            PACK2(b01, wv.x, wv.y);
            PACK2(b23, wv.z, wv.w);
            float4 xa = *(const float4*)&xt[kk * XT_STRIDE + m0];
            float4 xb = *(const float4*)&xt[kk * XT_STRIDE + m0 + 4];
            float xr[8] = {xa.x, xa.y, xa.z, xa.w, xb.x, xb.y, xb.z, xb.w};
#pragma unroll
            for (int i = 0; i < 8; i++) {
                ull av;
                PACK2(av, xr[i], xr[i]);
                FMA2(a01[i], av, b01, a01[i]);
                FMA2(a23[i], av, b23, a23[i]);
            }
        }
    }

#pragma unroll
    for (int i = 0; i < 8; i++) {
        int gm = m_base + m0 + i;
        if (gm < N) {
            float4 hv;
            UNPACK2(hv.x, hv.y, a01[i]);
            UNPACK2(hv.z, hv.w, a23[i]);
            *(float4*)&g_h[(size_t)gm * DIM + c0] = hv;
        }
    }
}

// ---------------------------------------------------------------------------
// Gather: one warp per destination node. Lane l owns floats [4l, 4l+4).
// Edge descriptors read broadcast (same addr all lanes); unroll x4 for MLP.
// ---------------------------------------------------------------------------
__global__ __launch_bounds__(256) void k_gather(float* __restrict__ out, int N) {
    int gtid = blockIdx.x * blockDim.x + threadIdx.x;
    int i = gtid >> 5;
    int lane = gtid & 31;
    if (i >= N) return;

    float di = g_dinv[i];
    float4 hv = ((const float4*)(g_h + (size_t)i * DIM))[lane];
    float s = di * di;  // self-loop weight
    float4 acc = make_float4(hv.x * s, hv.y * s, hv.z * s, hv.w * s);

    int j   = g_rowptr[i];
    int end = g_rowend[i];

    for (; j + 4 <= end; j += 4) {
        int2 e0 = g_edge[j + 0];
        int2 e1 = g_edge[j + 1];
        int2 e2 = g_edge[j + 2];
        int2 e3 = g_edge[j + 3];
        float4 n0 = ((const float4*)(g_h + (size_t)e0.x * DIM))[lane];
        float4 n1 = ((const float4*)(g_h + (size_t)e1.x * DIM))[lane];
        float4 n2 = ((const float4*)(g_h + (size_t)e2.x * DIM))[lane];
        float4 n3 = ((const float4*)(g_h + (size_t)e3.x * DIM))[lane];
        float w0 = di * __int_as_float(e0.y);
        float w1 = di * __int_as_float(e1.y);
        float w2 = di * __int_as_float(e2.y);
        float w3 = di * __int_as_float(e3.y);
        acc.x += w0 * n0.x + w1 * n1.x + w2 * n2.x + w3 * n3.x;
        acc.y += w0 * n0.y + w1 * n1.y + w2 * n2.y + w3 * n3.y;
        acc.z += w0 * n0.z + w1 * n1.z + w2 * n2.z + w3 * n3.z;
        acc.w += w0 * n0.w + w1 * n1.w + w2 * n2.w + w3 * n3.w;
    }
    for (; j < end; j++) {
        int2 e = g_edge[j];
        float4 nv = ((const float4*)(g_h + (size_t)e.x * DIM))[lane];
        float w = di * __int_as_float(e.y);
        acc.x += w * nv.x;
        acc.y += w * nv.y;
        acc.z += w * nv.z;
        acc.w += w * nv.w;
    }

    acc.x = fmaxf(acc.x, 0.0f);
    acc.y = fmaxf(acc.y, 0.0f);
    acc.z = fmaxf(acc.z, 0.0f);
    acc.w = fmaxf(acc.w, 0.0f);
    ((float4*)(out + (size_t)i * DIM))[lane] = acc;
}

// ---------------------------------------------------------------------------
extern "C" void kernel_launch(void* const* d_in, const int* in_sizes, int n_in,
                              void* d_out, int out_size) {
    const float* x  = (const float*)d_in[0];
    const float* W  = (const float*)d_in[1];
    const int*   ei = (const int*)d_in[2];   // int32 words; int64 via g_is64
    float* out      = (float*)d_out;

    int N = in_sizes[0] / DIM;
    int E = in_sizes[2] / 2;

    k_prep<<<(N + 255) / 256, 256>>>(ei, in_sizes[2], N);
    k_count<<<(E + 255) / 256, 256>>>(ei, E);
    k_alloc<<<(N + 255) / 256, 256>>>(N);
    k_fill<<<(E + 255) / 256, 256>>>(ei, E);
    k_gemm<<<(N + TM - 1) / TM, 256>>>(x, W, N);
    k_gather<<<(N * 32 + 255) / 256, 256>>>(out, N);
}